// round 1
// baseline (speedup 1.0000x reference)
#include <cuda_runtime.h>
#include <math.h>

#define BATCH  2
#define SEQ    2048
#define DMODEL 1024
#define NH     16
#define HD     64

// Scratch for Q, K, V in [B, H, S, HD] layout. __device__ globals (no allocation).
__device__ float g_q[BATCH * NH * SEQ * HD];
__device__ float g_k[BATCH * NH * SEQ * HD];
__device__ float g_v[BATCH * NH * SEQ * HD];

// ---------------------------------------------------------------------------
// QKV projection: out[b,h,s,hd] = (X @ W + bias), X: [4096, 1024], W: [1024, 1024]
// 64x64 tile, BK=16, 256 threads, 4x4 per thread.
// ---------------------------------------------------------------------------
__global__ __launch_bounds__(256) void qkv_proj_kernel(
    const float* __restrict__ X,
    const float* __restrict__ W,
    const float* __restrict__ bias,
    int sel)
{
    __shared__ float As[16][64];   // As[k][m] (A transposed in smem)
    __shared__ float Bs[16][64];   // Bs[k][n]

    float* outp = (sel == 0) ? g_q : (sel == 1) ? g_k : g_v;

    const int t  = threadIdx.x;
    const int tx = t & 15;
    const int ty = t >> 4;
    const int m0 = blockIdx.y * 64;
    const int n0 = blockIdx.x * 64;

    const int arow = t >> 2;            // 0..63
    const int akc  = (t & 3) << 2;      // 0,4,8,12
    const int brow = t >> 4;            // 0..15
    const int bnc  = (t & 15) << 2;     // 0..60

    float acc[4][4] = {};

    for (int k0 = 0; k0 < DMODEL; k0 += 16) {
        float4 a  = *(const float4*)&X[(size_t)(m0 + arow) * DMODEL + k0 + akc];
        float4 bb = *(const float4*)&W[(size_t)(k0 + brow) * DMODEL + n0 + bnc];
        __syncthreads();
        As[akc + 0][arow] = a.x;
        As[akc + 1][arow] = a.y;
        As[akc + 2][arow] = a.z;
        As[akc + 3][arow] = a.w;
        *(float4*)&Bs[brow][bnc] = bb;
        __syncthreads();
        #pragma unroll
        for (int kk = 0; kk < 16; kk++) {
            float4 av = *(const float4*)&As[kk][ty << 2];
            float4 bv = *(const float4*)&Bs[kk][tx << 2];
            acc[0][0] += av.x * bv.x; acc[0][1] += av.x * bv.y;
            acc[0][2] += av.x * bv.z; acc[0][3] += av.x * bv.w;
            acc[1][0] += av.y * bv.x; acc[1][1] += av.y * bv.y;
            acc[1][2] += av.y * bv.z; acc[1][3] += av.y * bv.w;
            acc[2][0] += av.z * bv.x; acc[2][1] += av.z * bv.y;
            acc[2][2] += av.z * bv.z; acc[2][3] += av.z * bv.w;
            acc[3][0] += av.w * bv.x; acc[3][1] += av.w * bv.y;
            acc[3][2] += av.w * bv.z; acc[3][3] += av.w * bv.w;
        }
    }

    #pragma unroll
    for (int i = 0; i < 4; i++) {
        int m = m0 + (ty << 2) + i;
        int b = m >> 11;            // m / SEQ
        int s = m & 2047;           // m % SEQ
        #pragma unroll
        for (int j = 0; j < 4; j++) {
            int n  = n0 + (tx << 2) + j;
            int h  = n >> 6;
            int hd = n & 63;
            outp[(((size_t)(b * NH + h)) * SEQ + s) * HD + hd] = acc[i][j] + bias[n];
        }
    }
}

// ---------------------------------------------------------------------------
// Flash attention, fp32: one CTA per (b*h, 64-query tile).
// Online softmax over key tiles of 64. 256 threads, 4x4 per thread.
// ---------------------------------------------------------------------------
__global__ __launch_bounds__(256) void attn_kernel(
    const float* __restrict__ mask,
    float* __restrict__ out)
{
    // dynamic smem layout (floats):
    //   Qs[64][65]  @ 0
    //   Ks[64][65]  @ 4160
    //   Ps[64][65]  @ 8320
    //   Vs[64][64]  @ 12480     (unpadded: float4-aligned rows)
    extern __shared__ float sm[];
    float (*Qs)[65] = (float(*)[65])(sm);
    float (*Ks)[65] = (float(*)[65])(sm + 4160);
    float (*Ps)[65] = (float(*)[65])(sm + 8320);
    float (*Vs)[64] = (float(*)[64])(sm + 12480);
    __shared__ float msk[64];

    const int t  = threadIdx.x;
    const int tx = t & 15;
    const int ty = t >> 4;
    const int bh = blockIdx.y;
    const int b  = bh >> 4;
    const int h  = bh & 15;
    const int q0 = blockIdx.x << 6;

    const float* Qb = g_q + ((size_t)bh * SEQ + q0) * HD;
    const float* Kb = g_k + (size_t)bh * SEQ * HD;
    const float* Vb = g_v + (size_t)bh * SEQ * HD;
    const float* mb = mask + (size_t)b * SEQ;

    // load Q tile (64x64)
    #pragma unroll
    for (int rep = 0; rep < 4; rep++) {
        int e   = t + rep * 256;
        int row = e >> 4;
        int c0  = (e & 15) << 2;
        float4 v = *(const float4*)&Qb[row * HD + c0];
        Qs[row][c0 + 0] = v.x;
        Qs[row][c0 + 1] = v.y;
        Qs[row][c0 + 2] = v.z;
        Qs[row][c0 + 3] = v.w;
    }

    float o[4][4] = {};
    float mr[4], lr[4];
    #pragma unroll
    for (int i = 0; i < 4; i++) { mr[i] = -3.0e38f; lr[i] = 0.0f; }

    const int r0  = ty << 2;
    const int c0t = tx << 2;

    for (int kt = 0; kt < SEQ; kt += 64) {
        __syncthreads();   // protect smem (prev PV reads / Q load) before refill
        #pragma unroll
        for (int rep = 0; rep < 4; rep++) {
            int e   = t + rep * 256;
            int row = e >> 4;
            int c0  = (e & 15) << 2;
            float4 kv = *(const float4*)&Kb[(kt + row) * HD + c0];
            Ks[row][c0 + 0] = kv.x;
            Ks[row][c0 + 1] = kv.y;
            Ks[row][c0 + 2] = kv.z;
            Ks[row][c0 + 3] = kv.w;
            float4 vv = *(const float4*)&Vb[(kt + row) * HD + c0];
            *(float4*)&Vs[row][c0] = vv;
        }
        if (t < 64) msk[t] = mb[kt + t];
        __syncthreads();

        // scores s[i][j] = sum_d Q[r0+i][d] * K[c0t+j][d]
        float s[4][4] = {};
        #pragma unroll 8
        for (int d = 0; d < 64; d++) {
            float q0v = Qs[r0 + 0][d];
            float q1v = Qs[r0 + 1][d];
            float q2v = Qs[r0 + 2][d];
            float q3v = Qs[r0 + 3][d];
            float k0v = Ks[c0t + 0][d];
            float k1v = Ks[c0t + 1][d];
            float k2v = Ks[c0t + 2][d];
            float k3v = Ks[c0t + 3][d];
            s[0][0] += q0v * k0v; s[0][1] += q0v * k1v; s[0][2] += q0v * k2v; s[0][3] += q0v * k3v;
            s[1][0] += q1v * k0v; s[1][1] += q1v * k1v; s[1][2] += q1v * k2v; s[1][3] += q1v * k3v;
            s[2][0] += q2v * k0v; s[2][1] += q2v * k1v; s[2][2] += q2v * k2v; s[2][3] += q2v * k3v;
            s[3][0] += q3v * k0v; s[3][1] += q3v * k1v; s[3][2] += q3v * k2v; s[3][3] += q3v * k3v;
        }

        // scale + additive mask
        #pragma unroll
        for (int i = 0; i < 4; i++)
            #pragma unroll
            for (int j = 0; j < 4; j++)
                s[i][j] = s[i][j] * 0.125f + msk[c0t + j];

        // online softmax per row (row owned by 16 lanes: same ty, tx 0..15)
        #pragma unroll
        for (int i = 0; i < 4; i++) {
            float tm = fmaxf(fmaxf(s[i][0], s[i][1]), fmaxf(s[i][2], s[i][3]));
            tm = fmaxf(tm, __shfl_xor_sync(0xffffffffu, tm, 1));
            tm = fmaxf(tm, __shfl_xor_sync(0xffffffffu, tm, 2));
            tm = fmaxf(tm, __shfl_xor_sync(0xffffffffu, tm, 4));
            tm = fmaxf(tm, __shfl_xor_sync(0xffffffffu, tm, 8));
            float mnew = fmaxf(mr[i], tm);
            float corr = __expf(mr[i] - mnew);
            float psum = 0.0f;
            #pragma unroll
            for (int j = 0; j < 4; j++) {
                s[i][j] = __expf(s[i][j] - mnew);
                psum += s[i][j];
            }
            psum += __shfl_xor_sync(0xffffffffu, psum, 1);
            psum += __shfl_xor_sync(0xffffffffu, psum, 2);
            psum += __shfl_xor_sync(0xffffffffu, psum, 4);
            psum += __shfl_xor_sync(0xffffffffu, psum, 8);
            lr[i] = lr[i] * corr + psum;
            mr[i] = mnew;
            #pragma unroll
            for (int j = 0; j < 4; j++) o[i][j] *= corr;
            #pragma unroll
            for (int j = 0; j < 4; j++) Ps[r0 + i][c0t + j] = s[i][j];
        }
        __syncwarp();   // P rows are produced & consumed within one warp

        // PV: o[i][j] += sum_k Ps[r0+i][k] * Vs[k][c0t+j]
        #pragma unroll 8
        for (int k = 0; k < 64; k++) {
            float4 vv = *(const float4*)&Vs[k][c0t];
            float p0 = Ps[r0 + 0][k];
            float p1 = Ps[r0 + 1][k];
            float p2 = Ps[r0 + 2][k];
            float p3 = Ps[r0 + 3][k];
            o[0][0] += p0 * vv.x; o[0][1] += p0 * vv.y; o[0][2] += p0 * vv.z; o[0][3] += p0 * vv.w;
            o[1][0] += p1 * vv.x; o[1][1] += p1 * vv.y; o[1][2] += p1 * vv.z; o[1][3] += p1 * vv.w;
            o[2][0] += p2 * vv.x; o[2][1] += p2 * vv.y; o[2][2] += p2 * vv.z; o[2][3] += p2 * vv.w;
            o[3][0] += p3 * vv.x; o[3][1] += p3 * vv.y; o[3][2] += p3 * vv.z; o[3][3] += p3 * vv.w;
        }
    }

    // epilogue: out[b, q0+r, h*64 + c] = o / l
    #pragma unroll
    for (int i = 0; i < 4; i++) {
        float inv = 1.0f / lr[i];
        int srow  = q0 + r0 + i;
        float4 res;
        res.x = o[i][0] * inv;
        res.y = o[i][1] * inv;
        res.z = o[i][2] * inv;
        res.w = o[i][3] * inv;
        *(float4*)&out[((size_t)b * SEQ + srow) * DMODEL + h * HD + c0t] = res;
    }
}

// ---------------------------------------------------------------------------
extern "C" void kernel_launch(void* const* d_in, const int* in_sizes, int n_in,
                              void* d_out, int out_size)
{
    (void)in_sizes; (void)n_in; (void)out_size;
    const float* X    = (const float*)d_in[0];
    const float* mask = (const float*)d_in[1];
    const float* Wq   = (const float*)d_in[2];
    const float* bq   = (const float*)d_in[3];
    const float* Wk   = (const float*)d_in[4];
    const float* bk   = (const float*)d_in[5];
    const float* Wv   = (const float*)d_in[6];
    const float* bv   = (const float*)d_in[7];
    float* out = (float*)d_out;

    dim3 gg(16, 64);   // N tiles x M tiles
    qkv_proj_kernel<<<gg, 256>>>(X, Wq, bq, 0);
    qkv_proj_kernel<<<gg, 256>>>(X, Wk, bk, 1);
    qkv_proj_kernel<<<gg, 256>>>(X, Wv, bv, 2);

    const int dyn_smem = 16576 * 4;   // 66,304 B
    cudaFuncSetAttribute(attn_kernel, cudaFuncAttributeMaxDynamicSharedMemorySize, dyn_smem);
    attn_kernel<<<dim3(32, 32), 256, dyn_smem>>>(mask, out);
}

// round 5
// speedup vs baseline: 1.1677x; 1.1677x over previous
#include <cuda_runtime.h>
#include <cuda_bf16.h>
#include <cstdint>
#include <math.h>

#define BATCH  2
#define SEQ    2048
#define DMODEL 1024
#define NH     16
#define HD     64

// Scratch for Q, K, V in [B, H, S, HD] layout. __device__ globals (no allocation).
__device__ float g_q[BATCH * NH * SEQ * HD];
__device__ float g_k[BATCH * NH * SEQ * HD];
__device__ float g_v[BATCH * NH * SEQ * HD];

__device__ __forceinline__ uint32_t bf2u(__nv_bfloat16 a, __nv_bfloat16 b) {
    __nv_bfloat162 t; t.x = a; t.y = b;
    return *reinterpret_cast<uint32_t*>(&t);
}
__device__ __forceinline__ void split_bf16(float v, __nv_bfloat16& h, __nv_bfloat16& l) {
    h = __float2bfloat16(v);
    l = __float2bfloat16(v - __bfloat162float(h));
}

__device__ __forceinline__ void mma_bf16(float* d, const uint32_t* a, const uint32_t* b) {
    asm volatile(
        "mma.sync.aligned.m16n8k16.row.col.f32.bf16.bf16.f32 "
        "{%0,%1,%2,%3}, {%4,%5,%6,%7}, {%8,%9}, {%0,%1,%2,%3};"
        : "+f"(d[0]), "+f"(d[1]), "+f"(d[2]), "+f"(d[3])
        : "r"(a[0]), "r"(a[1]), "r"(a[2]), "r"(a[3]), "r"(b[0]), "r"(b[1]));
}

// ============================================================================
// Fused QKV projection on mma.sync (split-bf16 3-term fp32 emulation).
// C[4096,1024] = X @ W_sel + b_sel, scattered into [B,H,S,HD].
// CTA tile 128x128, BK=32, double-buffered smem, 8 warps of 64x32.
// gridDim.z = sel (0=Q, 1=K, 2=V).
// ============================================================================
#define BK 32
#define NSTEP (DMODEL / BK)          // 32
#define APAD_K 40                    // row stride in bf16 (32 + 8 pad)
#define TILE_HB (128 * APAD_K)       // one tile in bf16 elems: 5120 (10240 B)
// smem layout (bf16 elems), per buffer: Ah, Al, Bh, Bl
#define QKV_SMEM_BYTES (2 * 4 * TILE_HB * 2)   // 81920

__global__ __launch_bounds__(256, 1) void qkv_mma_kernel(
    const float* __restrict__ X,
    const float* __restrict__ Wq, const float* __restrict__ bq,
    const float* __restrict__ Wk, const float* __restrict__ bk,
    const float* __restrict__ Wv, const float* __restrict__ bv)
{
    extern __shared__ __nv_bfloat16 smem[];
    const int sel = blockIdx.z;
    const float* W    = (sel == 0) ? Wq : (sel == 1) ? Wk : Wv;
    const float* bias = (sel == 0) ? bq : (sel == 1) ? bk : bv;
    float* outp       = (sel == 0) ? g_q : (sel == 1) ? g_k : g_v;

    const int t    = threadIdx.x;
    const int lane = t & 31;
    const int w    = t >> 5;
    const int m0   = blockIdx.y * 128;
    const int n0   = blockIdx.x * 128;
    const int wm   = (w >> 2) * 64;   // warp m offset within tile
    const int wn   = (w & 3) * 32;    // warp n offset within tile

    __nv_bfloat16* Ah[2]; __nv_bfloat16* Al[2];
    __nv_bfloat16* Bh[2]; __nv_bfloat16* Bl[2];
    #pragma unroll
    for (int bf = 0; bf < 2; bf++) {
        __nv_bfloat16* base = smem + bf * 4 * TILE_HB;
        Ah[bf] = base;
        Al[bf] = base + TILE_HB;
        Bh[bf] = base + 2 * TILE_HB;
        Bl[bf] = base + 3 * TILE_HB;
    }

    // staging indices
    const int arow = t >> 1;             // 0..127
    const int akc0 = (t & 1) * 16;       // 0 or 16
    const int bn   = t & 127;            // 0..127
    const int bkc0 = (t >> 7) * 16;      // 0 or 16

    float lda[16];
    float ldb[16];

    auto gload = [&](int ks) {
        const float* xr = X + (size_t)(m0 + arow) * DMODEL + ks * BK + akc0;
        #pragma unroll
        for (int i = 0; i < 4; i++)
            *(float4*)&lda[i * 4] = *(const float4*)(xr + i * 4);
        const float* wr = W + (size_t)(ks * BK + bkc0) * DMODEL + n0 + bn;
        #pragma unroll
        for (int i = 0; i < 16; i++)
            ldb[i] = wr[(size_t)i * DMODEL];
    };
    auto sstore = [&](int bf) {
        // A: row-major [row][k]
        #pragma unroll
        for (int i = 0; i < 4; i++) {
            __nv_bfloat16 h0, h1, h2, h3, l0, l1, l2, l3;
            split_bf16(lda[i*4+0], h0, l0); split_bf16(lda[i*4+1], h1, l1);
            split_bf16(lda[i*4+2], h2, l2); split_bf16(lda[i*4+3], h3, l3);
            int off = arow * APAD_K + akc0 + i * 4;
            uint2 hp, lp;
            hp.x = bf2u(h0, h1); hp.y = bf2u(h2, h3);
            lp.x = bf2u(l0, l1); lp.y = bf2u(l2, l3);
            *(uint2*)&Ah[bf][off] = hp;
            *(uint2*)&Al[bf][off] = lp;
        }
        // B: [n][k]
        #pragma unroll
        for (int i = 0; i < 16; i += 2) {
            __nv_bfloat16 h0, h1, l0, l1;
            split_bf16(ldb[i],     h0, l0);
            split_bf16(ldb[i + 1], h1, l1);
            int off = bn * APAD_K + bkc0 + i;
            *(uint32_t*)&Bh[bf][off] = bf2u(h0, h1);
            *(uint32_t*)&Bl[bf][off] = bf2u(l0, l1);
        }
    };

    float acc[4][4][4] = {};   // [mt][nt][4]

    gload(0);
    sstore(0);
    __syncthreads();

    for (int ks = 0; ks < NSTEP; ks++) {
        const int cur = ks & 1;
        if (ks + 1 < NSTEP) gload(ks + 1);

        #pragma unroll
        for (int kk = 0; kk < BK; kk += 16) {
            // A frags for 4 m-tiles
            uint32_t ah[4][4], al[4][4];
            #pragma unroll
            for (int mt = 0; mt < 4; mt++) {
                int r = wm + mt * 16 + (lane >> 2);
                int k = kk + (lane & 3) * 2;
                int o0 = r * APAD_K + k;
                int o1 = (r + 8) * APAD_K + k;
                ah[mt][0] = *(uint32_t*)&Ah[cur][o0];
                ah[mt][1] = *(uint32_t*)&Ah[cur][o1];
                ah[mt][2] = *(uint32_t*)&Ah[cur][o0 + 8];
                ah[mt][3] = *(uint32_t*)&Ah[cur][o1 + 8];
                al[mt][0] = *(uint32_t*)&Al[cur][o0];
                al[mt][1] = *(uint32_t*)&Al[cur][o1];
                al[mt][2] = *(uint32_t*)&Al[cur][o0 + 8];
                al[mt][3] = *(uint32_t*)&Al[cur][o1 + 8];
            }
            #pragma unroll
            for (int nt = 0; nt < 4; nt++) {
                int n = wn + nt * 8 + (lane >> 2);
                int k = kk + (lane & 3) * 2;
                int o = n * APAD_K + k;
                uint32_t bh[2], bl[2];
                bh[0] = *(uint32_t*)&Bh[cur][o];
                bh[1] = *(uint32_t*)&Bh[cur][o + 8];
                bl[0] = *(uint32_t*)&Bl[cur][o];
                bl[1] = *(uint32_t*)&Bl[cur][o + 8];
                #pragma unroll
                for (int mt = 0; mt < 4; mt++) {
                    mma_bf16(acc[mt][nt], ah[mt], bh);
                    mma_bf16(acc[mt][nt], ah[mt], bl);
                    mma_bf16(acc[mt][nt], al[mt], bh);
                }
            }
        }

        if (ks + 1 < NSTEP) {
            sstore((ks + 1) & 1);
            __syncthreads();
        }
    }

    // Epilogue: D layout per thread: rows lane/4 + {0,8}, cols 2*(lane%4) + {0,1}
    #pragma unroll
    for (int mt = 0; mt < 4; mt++) {
        #pragma unroll
        for (int half = 0; half < 2; half++) {
            int m = m0 + wm + mt * 16 + (lane >> 2) + half * 8;
            int b = m >> 11;
            int s = m & 2047;
            float* orow = outp + (((size_t)b * NH) * SEQ + s) * HD;  // + h*SEQ*HD later
            #pragma unroll
            for (int nt = 0; nt < 4; nt++) {
                int ncol = n0 + wn + nt * 8 + ((lane & 3) << 1);
                int h  = ncol >> 6;
                int hd = ncol & 63;
                float2 r2;
                r2.x = acc[mt][nt][half * 2 + 0] + bias[ncol];
                r2.y = acc[mt][nt][half * 2 + 1] + bias[ncol + 1];
                *(float2*)&orow[(size_t)h * SEQ * HD + hd] = r2;
            }
        }
    }
}

// ============================================================================
// Flash attention, fp32 SIMT, K transposed in smem for conflict-free float4.
// One CTA per (b*h, 64-query tile). 256 threads, 4x4 per thread.
// ============================================================================
#define QP_STRIDE 68    // row stride (floats) for Qs/Ps
#define KT_STRIDE 68    // row stride for Kt [d][s]

__global__ __launch_bounds__(256) void attn_kernel(
    const float* __restrict__ mask,
    float* __restrict__ out)
{
    // dynamic smem (floats): Qs[64][68] @0, Kt[64][68] @4352, Ps[64][68] @8704, Vs[64][64] @13056
    extern __shared__ float sm[];
    float (*Qs)[QP_STRIDE] = (float(*)[QP_STRIDE])(sm);
    float (*Kt)[KT_STRIDE] = (float(*)[KT_STRIDE])(sm + 4352);
    float (*Ps)[QP_STRIDE] = (float(*)[QP_STRIDE])(sm + 8704);
    float (*Vs)[64]        = (float(*)[64])(sm + 13056);
    __shared__ float msk[64];

    const int t  = threadIdx.x;
    const int tx = t & 15;
    const int ty = t >> 4;
    const int bh = blockIdx.y;
    const int b  = bh >> 4;
    const int h  = bh & 15;
    const int q0 = blockIdx.x << 6;

    const float* Qb = g_q + ((size_t)bh * SEQ + q0) * HD;
    const float* Kb = g_k + (size_t)bh * SEQ * HD;
    const float* Vb = g_v + (size_t)bh * SEQ * HD;
    const float* mb = mask + (size_t)b * SEQ;

    // load Q tile (64x64)
    #pragma unroll
    for (int rep = 0; rep < 4; rep++) {
        int e   = t + rep * 256;
        int row = e >> 4;
        int c0  = (e & 15) << 2;
        *(float4*)&Qs[row][c0] = *(const float4*)&Qb[row * HD + c0];
    }

    float o[4][4] = {};
    float mr[4], lr[4];
    #pragma unroll
    for (int i = 0; i < 4; i++) { mr[i] = -3.0e38f; lr[i] = 0.0f; }

    const int r0  = ty << 4 >> 2;   // ty*4
    const int c0t = tx << 2;

    for (int kt = 0; kt < SEQ; kt += 64) {
        __syncthreads();
        #pragma unroll
        for (int rep = 0; rep < 4; rep++) {
            int e   = t + rep * 256;
            int row = e >> 4;
            int c0  = (e & 15) << 2;
            float4 kv = *(const float4*)&Kb[(kt + row) * HD + c0];
            Kt[c0 + 0][row] = kv.x;
            Kt[c0 + 1][row] = kv.y;
            Kt[c0 + 2][row] = kv.z;
            Kt[c0 + 3][row] = kv.w;
            *(float4*)&Vs[row][c0] = *(const float4*)&Vb[(kt + row) * HD + c0];
        }
        if (t < 64) msk[t] = mb[kt + t];
        __syncthreads();

        // scores s[i][j] = sum_d Q[r0+i][d] * Kt[d][c0t+j]
        float s[4][4] = {};
        #pragma unroll 8
        for (int d = 0; d < 64; d++) {
            float4 kv = *(const float4*)&Kt[d][c0t];
            float qv0 = Qs[r0 + 0][d];
            float qv1 = Qs[r0 + 1][d];
            float qv2 = Qs[r0 + 2][d];
            float qv3 = Qs[r0 + 3][d];
            s[0][0] += qv0 * kv.x; s[0][1] += qv0 * kv.y; s[0][2] += qv0 * kv.z; s[0][3] += qv0 * kv.w;
            s[1][0] += qv1 * kv.x; s[1][1] += qv1 * kv.y; s[1][2] += qv1 * kv.z; s[1][3] += qv1 * kv.w;
            s[2][0] += qv2 * kv.x; s[2][1] += qv2 * kv.y; s[2][2] += qv2 * kv.z; s[2][3] += qv2 * kv.w;
            s[3][0] += qv3 * kv.x; s[3][1] += qv3 * kv.y; s[3][2] += qv3 * kv.z; s[3][3] += qv3 * kv.w;
        }

        // scale + additive mask
        #pragma unroll
        for (int i = 0; i < 4; i++)
            #pragma unroll
            for (int j = 0; j < 4; j++)
                s[i][j] = s[i][j] * 0.125f + msk[c0t + j];

        // online softmax per row (row owned by 16 lanes of one warp half)
        #pragma unroll
        for (int i = 0; i < 4; i++) {
            float tm = fmaxf(fmaxf(s[i][0], s[i][1]), fmaxf(s[i][2], s[i][3]));
            tm = fmaxf(tm, __shfl_xor_sync(0xffffffffu, tm, 1));
            tm = fmaxf(tm, __shfl_xor_sync(0xffffffffu, tm, 2));
            tm = fmaxf(tm, __shfl_xor_sync(0xffffffffu, tm, 4));
            tm = fmaxf(tm, __shfl_xor_sync(0xffffffffu, tm, 8));
            float mnew = fmaxf(mr[i], tm);
            float corr = __expf(mr[i] - mnew);
            float psum = 0.0f;
            #pragma unroll
            for (int j = 0; j < 4; j++) {
                s[i][j] = __expf(s[i][j] - mnew);
                psum += s[i][j];
            }
            psum += __shfl_xor_sync(0xffffffffu, psum, 1);
            psum += __shfl_xor_sync(0xffffffffu, psum, 2);
            psum += __shfl_xor_sync(0xffffffffu, psum, 4);
            psum += __shfl_xor_sync(0xffffffffu, psum, 8);
            lr[i] = lr[i] * corr + psum;
            mr[i] = mnew;
            #pragma unroll
            for (int j = 0; j < 4; j++) o[i][j] *= corr;
            *(float4*)&Ps[r0 + i][c0t] = *(float4*)&s[i][0];
        }
        __syncwarp();   // P rows produced & consumed within one warp

        // PV: o[i][j] += sum_k Ps[r0+i][k] * Vs[k][c0t+j]
        #pragma unroll 4
        for (int k = 0; k < 64; k += 4) {
            float4 pv[4], vv[4];
            #pragma unroll
            for (int i = 0; i < 4; i++) pv[i] = *(const float4*)&Ps[r0 + i][k];
            #pragma unroll
            for (int kk = 0; kk < 4; kk++) vv[kk] = *(const float4*)&Vs[k + kk][c0t];
            #pragma unroll
            for (int i = 0; i < 4; i++) {
                o[i][0] += pv[i].x * vv[0].x + pv[i].y * vv[1].x + pv[i].z * vv[2].x + pv[i].w * vv[3].x;
                o[i][1] += pv[i].x * vv[0].y + pv[i].y * vv[1].y + pv[i].z * vv[2].y + pv[i].w * vv[3].y;
                o[i][2] += pv[i].x * vv[0].z + pv[i].y * vv[1].z + pv[i].z * vv[2].z + pv[i].w * vv[3].z;
                o[i][3] += pv[i].x * vv[0].w + pv[i].y * vv[1].w + pv[i].z * vv[2].w + pv[i].w * vv[3].w;
            }
        }
    }

    // epilogue
    #pragma unroll
    for (int i = 0; i < 4; i++) {
        float inv = 1.0f / lr[i];
        int srow  = q0 + r0 + i;
        float4 res;
        res.x = o[i][0] * inv;
        res.y = o[i][1] * inv;
        res.z = o[i][2] * inv;
        res.w = o[i][3] * inv;
        *(float4*)&out[((size_t)b * SEQ + srow) * DMODEL + h * HD + c0t] = res;
    }
}

// ---------------------------------------------------------------------------
extern "C" void kernel_launch(void* const* d_in, const int* in_sizes, int n_in,
                              void* d_out, int out_size)
{
    (void)in_sizes; (void)n_in; (void)out_size;
    const float* X    = (const float*)d_in[0];
    const float* mask = (const float*)d_in[1];
    const float* Wq   = (const float*)d_in[2];
    const float* bq   = (const float*)d_in[3];
    const float* Wk   = (const float*)d_in[4];
    const float* bk   = (const float*)d_in[5];
    const float* Wv   = (const float*)d_in[6];
    const float* bv   = (const float*)d_in[7];
    float* out = (float*)d_out;

    cudaFuncSetAttribute(qkv_mma_kernel, cudaFuncAttributeMaxDynamicSharedMemorySize, QKV_SMEM_BYTES);
    dim3 gq(DMODEL / 128, (BATCH * SEQ) / 128, 3);   // (8, 32, 3)
    qkv_mma_kernel<<<gq, 256, QKV_SMEM_BYTES>>>(X, Wq, bq, Wk, bk, Wv, bv);

    const int attn_smem = (13056 + 4096) * 4;   // 68,608 B
    cudaFuncSetAttribute(attn_kernel, cudaFuncAttributeMaxDynamicSharedMemorySize, attn_smem);
    attn_kernel<<<dim3(SEQ / 64, BATCH * NH), 256, attn_smem>>>(mask, out);
}

// round 10
// speedup vs baseline: 1.7715x; 1.5170x over previous
#include <cuda_runtime.h>
#include <cuda_bf16.h>
#include <cstdint>
#include <math.h>

#define BATCH  2
#define SEQ    2048
#define DMODEL 1024
#define NH     16
#define HD     64

// Scratch for Q, K, V in [B, H, S, HD] layout. __device__ globals (no allocation).
__device__ float g_q[BATCH * NH * SEQ * HD];
__device__ float g_k[BATCH * NH * SEQ * HD];
__device__ float g_v[BATCH * NH * SEQ * HD];

__device__ __forceinline__ uint32_t bf2u(__nv_bfloat16 a, __nv_bfloat16 b) {
    __nv_bfloat162 t; t.x = a; t.y = b;
    return *reinterpret_cast<uint32_t*>(&t);
}
__device__ __forceinline__ void split_bf16(float v, __nv_bfloat16& h, __nv_bfloat16& l) {
    h = __float2bfloat16(v);
    l = __float2bfloat16(v - __bfloat162float(h));
}
// pack the high parts and low parts of two floats into two u32 bf16x2 words
__device__ __forceinline__ void split2_pack(float a, float b, uint32_t& hi, uint32_t& lo) {
    __nv_bfloat16 ha, la, hb, lb;
    split_bf16(a, ha, la);
    split_bf16(b, hb, lb);
    hi = bf2u(ha, hb);
    lo = bf2u(la, lb);
}

__device__ __forceinline__ void mma_bf16(float* d, const uint32_t* a, const uint32_t* b) {
    asm volatile(
        "mma.sync.aligned.m16n8k16.row.col.f32.bf16.bf16.f32 "
        "{%0,%1,%2,%3}, {%4,%5,%6,%7}, {%8,%9}, {%0,%1,%2,%3};"
        : "+f"(d[0]), "+f"(d[1]), "+f"(d[2]), "+f"(d[3])
        : "r"(a[0]), "r"(a[1]), "r"(a[2]), "r"(a[3]), "r"(b[0]), "r"(b[1]));
}

// ============================================================================
// Fused QKV projection on mma.sync (split-bf16 3-term fp32 emulation).
// CTA tile 128x128, BK=32, double-buffered smem, 8 warps of 64x32.
// gridDim.z = sel (0=Q, 1=K, 2=V).
// ============================================================================
#define BK 32
#define NSTEP (DMODEL / BK)          // 32
#define APAD_K 40                    // row stride in bf16 (32 + 8 pad)
#define TILE_HB (128 * APAD_K)       // 5120 bf16 (10240 B)
#define QKV_SMEM_BYTES (2 * 4 * TILE_HB * 2)   // 81920

__global__ __launch_bounds__(256, 1) void qkv_mma_kernel(
    const float* __restrict__ X,
    const float* __restrict__ Wq, const float* __restrict__ bq,
    const float* __restrict__ Wk, const float* __restrict__ bk,
    const float* __restrict__ Wv, const float* __restrict__ bv)
{
    extern __shared__ __nv_bfloat16 smem[];
    const int sel = blockIdx.z;
    const float* W    = (sel == 0) ? Wq : (sel == 1) ? Wk : Wv;
    const float* bias = (sel == 0) ? bq : (sel == 1) ? bk : bv;
    float* outp       = (sel == 0) ? g_q : (sel == 1) ? g_k : g_v;

    const int t    = threadIdx.x;
    const int lane = t & 31;
    const int w    = t >> 5;
    const int m0   = blockIdx.y * 128;
    const int n0   = blockIdx.x * 128;
    const int wm   = (w >> 2) * 64;
    const int wn   = (w & 3) * 32;

    __nv_bfloat16* Ah[2]; __nv_bfloat16* Al[2];
    __nv_bfloat16* Bh[2]; __nv_bfloat16* Bl[2];
    #pragma unroll
    for (int bf = 0; bf < 2; bf++) {
        __nv_bfloat16* base = smem + bf * 4 * TILE_HB;
        Ah[bf] = base;
        Al[bf] = base + TILE_HB;
        Bh[bf] = base + 2 * TILE_HB;
        Bl[bf] = base + 3 * TILE_HB;
    }

    const int arow = t >> 1;
    const int akc0 = (t & 1) * 16;
    const int bn   = t & 127;
    const int bkc0 = (t >> 7) * 16;

    float lda[16];
    float ldb[16];

    auto gload = [&](int ks) {
        const float* xr = X + (size_t)(m0 + arow) * DMODEL + ks * BK + akc0;
        #pragma unroll
        for (int i = 0; i < 4; i++)
            *(float4*)&lda[i * 4] = *(const float4*)(xr + i * 4);
        const float* wr = W + (size_t)(ks * BK + bkc0) * DMODEL + n0 + bn;
        #pragma unroll
        for (int i = 0; i < 16; i++)
            ldb[i] = wr[(size_t)i * DMODEL];
    };
    auto sstore = [&](int bf) {
        #pragma unroll
        for (int i = 0; i < 4; i++) {
            uint2 hp, lp;
            split2_pack(lda[i*4+0], lda[i*4+1], hp.x, lp.x);
            split2_pack(lda[i*4+2], lda[i*4+3], hp.y, lp.y);
            int off = arow * APAD_K + akc0 + i * 4;
            *(uint2*)&Ah[bf][off] = hp;
            *(uint2*)&Al[bf][off] = lp;
        }
        #pragma unroll
        for (int i = 0; i < 16; i += 2) {
            uint32_t hh, ll;
            split2_pack(ldb[i], ldb[i + 1], hh, ll);
            int off = bn * APAD_K + bkc0 + i;
            *(uint32_t*)&Bh[bf][off] = hh;
            *(uint32_t*)&Bl[bf][off] = ll;
        }
    };

    float acc[4][4][4] = {};

    gload(0);
    sstore(0);
    __syncthreads();

    for (int ks = 0; ks < NSTEP; ks++) {
        const int cur = ks & 1;
        if (ks + 1 < NSTEP) gload(ks + 1);

        #pragma unroll
        for (int kk = 0; kk < BK; kk += 16) {
            uint32_t ah[4][4], al[4][4];
            #pragma unroll
            for (int mt = 0; mt < 4; mt++) {
                int r = wm + mt * 16 + (lane >> 2);
                int k = kk + (lane & 3) * 2;
                int o0 = r * APAD_K + k;
                int o1 = (r + 8) * APAD_K + k;
                ah[mt][0] = *(uint32_t*)&Ah[cur][o0];
                ah[mt][1] = *(uint32_t*)&Ah[cur][o1];
                ah[mt][2] = *(uint32_t*)&Ah[cur][o0 + 8];
                ah[mt][3] = *(uint32_t*)&Ah[cur][o1 + 8];
                al[mt][0] = *(uint32_t*)&Al[cur][o0];
                al[mt][1] = *(uint32_t*)&Al[cur][o1];
                al[mt][2] = *(uint32_t*)&Al[cur][o0 + 8];
                al[mt][3] = *(uint32_t*)&Al[cur][o1 + 8];
            }
            #pragma unroll
            for (int nt = 0; nt < 4; nt++) {
                int n = wn + nt * 8 + (lane >> 2);
                int k = kk + (lane & 3) * 2;
                int o = n * APAD_K + k;
                uint32_t bh[2], bl[2];
                bh[0] = *(uint32_t*)&Bh[cur][o];
                bh[1] = *(uint32_t*)&Bh[cur][o + 8];
                bl[0] = *(uint32_t*)&Bl[cur][o];
                bl[1] = *(uint32_t*)&Bl[cur][o + 8];
                #pragma unroll
                for (int mt = 0; mt < 4; mt++) {
                    mma_bf16(acc[mt][nt], ah[mt], bh);
                    mma_bf16(acc[mt][nt], ah[mt], bl);
                    mma_bf16(acc[mt][nt], al[mt], bh);
                }
            }
        }

        if (ks + 1 < NSTEP) {
            sstore((ks + 1) & 1);
            __syncthreads();
        }
    }

    #pragma unroll
    for (int mt = 0; mt < 4; mt++) {
        #pragma unroll
        for (int half = 0; half < 2; half++) {
            int m = m0 + wm + mt * 16 + (lane >> 2) + half * 8;
            int b = m >> 11;
            int s = m & 2047;
            float* orow = outp + (((size_t)b * NH) * SEQ + s) * HD;
            #pragma unroll
            for (int nt = 0; nt < 4; nt++) {
                int ncol = n0 + wn + nt * 8 + ((lane & 3) << 1);
                int h  = ncol >> 6;
                int hd = ncol & 63;
                float2 r2;
                r2.x = acc[mt][nt][half * 2 + 0] + bias[ncol];
                r2.y = acc[mt][nt][half * 2 + 1] + bias[ncol + 1];
                *(float2*)&orow[(size_t)h * SEQ * HD + hd] = r2;
            }
        }
    }
}

// ============================================================================
// Flash attention on mma.sync. CTA = 64 q-rows x (b,h); 4 warps x 16 rows.
// KV tile 64. Q/K split-bf16 3-term; P split-bf16 3-term; V split-bf16.
// ============================================================================
#define KSTR 72   // bf16 row stride for K ([kv][hd]) and Vt ([hd][kv])

__global__ __launch_bounds__(128) void attn_mma_kernel(
    const float* __restrict__ mask,
    float* __restrict__ out)
{
    __shared__ __nv_bfloat16 Khs[64 * KSTR];
    __shared__ __nv_bfloat16 Kls[64 * KSTR];
    __shared__ __nv_bfloat16 Vth[64 * KSTR];   // [hd][kv]
    __shared__ __nv_bfloat16 Vtl[64 * KSTR];
    __shared__ float msk[64];

    const int t    = threadIdx.x;
    const int lane = t & 31;
    const int w    = t >> 5;
    const int lq   = lane >> 2;      // 0..7 (row within 8)
    const int lr   = lane & 3;       // 0..3 (pair col)
    const int bh   = blockIdx.y;
    const int b    = bh >> 4;
    const int h    = bh & 15;
    const int q0   = blockIdx.x << 6;

    const float* Qb = g_q + ((size_t)bh * SEQ + q0) * HD;
    const float* Kb = g_k + (size_t)bh * SEQ * HD;
    const float* Vb = g_v + (size_t)bh * SEQ * HD;
    const float* mb = mask + (size_t)b * SEQ;

    // ---- stage Q (64x64) split into Khs/Kls, then extract A-fragments ----
    {
        int row = t >> 1;
        int c0  = (t & 1) * 32;
        const float* qr = Qb + row * HD + c0;
        #pragma unroll
        for (int v = 0; v < 8; v++) {
            float4 q4 = *(const float4*)(qr + v * 4);
            uint2 hp, lp;
            split2_pack(q4.x, q4.y, hp.x, lp.x);
            split2_pack(q4.z, q4.w, hp.y, lp.y);
            int off = row * KSTR + c0 + v * 4;
            *(uint2*)&Khs[off] = hp;
            *(uint2*)&Kls[off] = lp;
        }
    }
    __syncthreads();

    uint32_t qh[4][4], ql[4][4];
    {
        int r = 16 * w + lq;
        #pragma unroll
        for (int t4 = 0; t4 < 4; t4++) {
            int k  = 16 * t4 + 2 * lr;
            int o0 = r * KSTR + k;
            int o1 = (r + 8) * KSTR + k;
            qh[t4][0] = *(uint32_t*)&Khs[o0];
            qh[t4][1] = *(uint32_t*)&Khs[o1];
            qh[t4][2] = *(uint32_t*)&Khs[o0 + 8];
            qh[t4][3] = *(uint32_t*)&Khs[o1 + 8];
            ql[t4][0] = *(uint32_t*)&Kls[o0];
            ql[t4][1] = *(uint32_t*)&Kls[o1];
            ql[t4][2] = *(uint32_t*)&Kls[o0 + 8];
            ql[t4][3] = *(uint32_t*)&Kls[o1 + 8];
        }
    }

    float o[8][4] = {};
    float mA = -1.0e30f, mB = -1.0e30f, lA = 0.0f, lB = 0.0f;

    for (int kt = 0; kt < SEQ; kt += 64) {
        __syncthreads();   // everyone done reading smem from prev iter / Q phase

        // ---- stage K tile (split, [kv][hd]) ----
        {
            int row = t >> 1;
            int c0  = (t & 1) * 32;
            const float* kr = Kb + (kt + row) * HD + c0;
            #pragma unroll
            for (int v = 0; v < 8; v++) {
                float4 k4 = *(const float4*)(kr + v * 4);
                uint2 hp, lp;
                split2_pack(k4.x, k4.y, hp.x, lp.x);
                split2_pack(k4.z, k4.w, hp.y, lp.y);
                int off = row * KSTR + c0 + v * 4;
                *(uint2*)&Khs[off] = hp;
                *(uint2*)&Kls[off] = lp;
            }
        }
        // ---- stage V tile transposed (split, [hd][kv]) ----
        {
            int rp = t >> 2;            // 0..31 -> kv rows 2rp, 2rp+1
            int c0 = (t & 3) * 16;
            const float* vr0 = Vb + (kt + 2 * rp) * HD + c0;
            const float* vr1 = vr0 + HD;
            float v0[16], v1[16];
            #pragma unroll
            for (int i = 0; i < 4; i++) {
                *(float4*)&v0[i * 4] = *(const float4*)(vr0 + i * 4);
                *(float4*)&v1[i * 4] = *(const float4*)(vr1 + i * 4);
            }
            #pragma unroll
            for (int i = 0; i < 16; i++) {
                uint32_t hh, ll;
                split2_pack(v0[i], v1[i], hh, ll);
                int off = (c0 + i) * KSTR + 2 * rp;
                *(uint32_t*)&Vth[off] = hh;
                *(uint32_t*)&Vtl[off] = ll;
            }
        }
        if (t < 64) msk[t] = mb[kt + t];
        __syncthreads();

        // ---- scores: s[j] (16x8 tile j), rows 16w..: 3-term split ----
        float s[8][4] = {};
        #pragma unroll
        for (int t4 = 0; t4 < 4; t4++) {
            #pragma unroll
            for (int j = 0; j < 8; j++) {
                int n = 8 * j + lq;
                int k = 16 * t4 + 2 * lr;
                int oo = n * KSTR + k;
                uint32_t bhf[2], blf[2];
                bhf[0] = *(uint32_t*)&Khs[oo];
                bhf[1] = *(uint32_t*)&Khs[oo + 8];
                blf[0] = *(uint32_t*)&Kls[oo];
                blf[1] = *(uint32_t*)&Kls[oo + 8];
                mma_bf16(s[j], qh[t4], bhf);
                mma_bf16(s[j], qh[t4], blf);
                mma_bf16(s[j], ql[t4], bhf);
            }
        }

        // ---- scale + mask ----
        #pragma unroll
        for (int j = 0; j < 8; j++) {
            float m0v = msk[8 * j + 2 * lr];
            float m1v = msk[8 * j + 2 * lr + 1];
            s[j][0] = s[j][0] * 0.125f + m0v;
            s[j][1] = s[j][1] * 0.125f + m1v;
            s[j][2] = s[j][2] * 0.125f + m0v;
            s[j][3] = s[j][3] * 0.125f + m1v;
        }

        // ---- online softmax (rowA = lq, rowB = lq+8; quad = lanes sharing row) ----
        float tmA = -1.0e30f, tmB = -1.0e30f;
        #pragma unroll
        for (int j = 0; j < 8; j++) {
            tmA = fmaxf(tmA, fmaxf(s[j][0], s[j][1]));
            tmB = fmaxf(tmB, fmaxf(s[j][2], s[j][3]));
        }
        tmA = fmaxf(tmA, __shfl_xor_sync(0xffffffffu, tmA, 1));
        tmA = fmaxf(tmA, __shfl_xor_sync(0xffffffffu, tmA, 2));
        tmB = fmaxf(tmB, __shfl_xor_sync(0xffffffffu, tmB, 1));
        tmB = fmaxf(tmB, __shfl_xor_sync(0xffffffffu, tmB, 2));
        float mAn = fmaxf(mA, tmA);
        float mBn = fmaxf(mB, tmB);
        float corrA = __expf(mA - mAn);
        float corrB = __expf(mB - mBn);
        float sumA = 0.0f, sumB = 0.0f;
        #pragma unroll
        for (int j = 0; j < 8; j++) {
            s[j][0] = __expf(s[j][0] - mAn);
            s[j][1] = __expf(s[j][1] - mAn);
            s[j][2] = __expf(s[j][2] - mBn);
            s[j][3] = __expf(s[j][3] - mBn);
            sumA += s[j][0] + s[j][1];
            sumB += s[j][2] + s[j][3];
        }
        sumA += __shfl_xor_sync(0xffffffffu, sumA, 1);
        sumA += __shfl_xor_sync(0xffffffffu, sumA, 2);
        sumB += __shfl_xor_sync(0xffffffffu, sumB, 1);
        sumB += __shfl_xor_sync(0xffffffffu, sumB, 2);
        lA = lA * corrA + sumA;
        lB = lB * corrB + sumB;
        mA = mAn;
        mB = mBn;
        #pragma unroll
        for (int j = 0; j < 8; j++) {
            o[j][0] *= corrA;
            o[j][1] *= corrA;
            o[j][2] *= corrB;
            o[j][3] *= corrB;
        }

        // ---- P fragments, SPLIT hi/lo (C-frag layout == A-frag layout) ----
        uint32_t pfh[4][4], pfl[4][4];
        #pragma unroll
        for (int t4 = 0; t4 < 4; t4++) {
            split2_pack(s[2*t4][0],   s[2*t4][1],   pfh[t4][0], pfl[t4][0]);
            split2_pack(s[2*t4][2],   s[2*t4][3],   pfh[t4][1], pfl[t4][1]);
            split2_pack(s[2*t4+1][0], s[2*t4+1][1], pfh[t4][2], pfl[t4][2]);
            split2_pack(s[2*t4+1][2], s[2*t4+1][3], pfh[t4][3], pfl[t4][3]);
        }

        // ---- PV: o += Ph*Vh + Ph*Vl + Pl*Vh (3-term) ----
        #pragma unroll
        for (int t4 = 0; t4 < 4; t4++) {
            #pragma unroll
            for (int j = 0; j < 8; j++) {
                int n = 8 * j + lq;              // hd
                int k = 16 * t4 + 2 * lr;        // kv
                int oo = n * KSTR + k;
                uint32_t vhf[2], vlf[2];
                vhf[0] = *(uint32_t*)&Vth[oo];
                vhf[1] = *(uint32_t*)&Vth[oo + 8];
                vlf[0] = *(uint32_t*)&Vtl[oo];
                vlf[1] = *(uint32_t*)&Vtl[oo + 8];
                mma_bf16(o[j], pfh[t4], vhf);
                mma_bf16(o[j], pfh[t4], vlf);
                mma_bf16(o[j], pfl[t4], vhf);
            }
        }
    }

    // ---- epilogue ----
    {
        float invA = 1.0f / lA;
        float invB = 1.0f / lB;
        int rA = q0 + 16 * w + lq;
        int rB = rA + 8;
        float* baseA = out + ((size_t)b * SEQ + rA) * DMODEL + h * HD;
        float* baseB = out + ((size_t)b * SEQ + rB) * DMODEL + h * HD;
        #pragma unroll
        for (int j = 0; j < 8; j++) {
            int col = 8 * j + 2 * lr;
            float2 ra, rb;
            ra.x = o[j][0] * invA; ra.y = o[j][1] * invA;
            rb.x = o[j][2] * invB; rb.y = o[j][3] * invB;
            *(float2*)&baseA[col] = ra;
            *(float2*)&baseB[col] = rb;
        }
    }
}

// ---------------------------------------------------------------------------
extern "C" void kernel_launch(void* const* d_in, const int* in_sizes, int n_in,
                              void* d_out, int out_size)
{
    (void)in_sizes; (void)n_in; (void)out_size;
    const float* X    = (const float*)d_in[0];
    const float* mask = (const float*)d_in[1];
    const float* Wq   = (const float*)d_in[2];
    const float* bq   = (const float*)d_in[3];
    const float* Wk   = (const float*)d_in[4];
    const float* bk   = (const float*)d_in[5];
    const float* Wv   = (const float*)d_in[6];
    const float* bv   = (const float*)d_in[7];
    float* out = (float*)d_out;

    cudaFuncSetAttribute(qkv_mma_kernel, cudaFuncAttributeMaxDynamicSharedMemorySize, QKV_SMEM_BYTES);
    dim3 gq(DMODEL / 128, (BATCH * SEQ) / 128, 3);
    qkv_mma_kernel<<<gq, 256, QKV_SMEM_BYTES>>>(X, Wq, bq, Wk, bk, Wv, bv);

    attn_mma_kernel<<<dim3(SEQ / 64, BATCH * NH), 128>>>(mask, out);
}

// round 11
// speedup vs baseline: 2.3893x; 1.3487x over previous
#include <cuda_runtime.h>
#include <cuda_bf16.h>
#include <cstdint>
#include <math.h>

#define BATCH  2
#define SEQ    2048
#define DMODEL 1024
#define NH     16
#define HD     64
#define NELEM  (BATCH * NH * SEQ * HD)

// Q, K, V in [B, H, S, HD] layout, pre-split into bf16 hi/lo pairs.
__device__ __nv_bfloat16 g_qh[NELEM], g_ql[NELEM];
__device__ __nv_bfloat16 g_kh[NELEM], g_kl[NELEM];
__device__ __nv_bfloat16 g_vh[NELEM], g_vl[NELEM];

// ---------------------------------------------------------------------------
__device__ __forceinline__ uint32_t bf2u(__nv_bfloat16 a, __nv_bfloat16 b) {
    __nv_bfloat162 t; t.x = a; t.y = b;
    return *reinterpret_cast<uint32_t*>(&t);
}
__device__ __forceinline__ void split_bf16(float v, __nv_bfloat16& h, __nv_bfloat16& l) {
    h = __float2bfloat16(v);
    l = __float2bfloat16(v - __bfloat162float(h));
}
__device__ __forceinline__ void split2_pack(float a, float b, uint32_t& hi, uint32_t& lo) {
    __nv_bfloat16 ha, la, hb, lb;
    split_bf16(a, ha, la);
    split_bf16(b, hb, lb);
    hi = bf2u(ha, hb);
    lo = bf2u(la, lb);
}
__device__ __forceinline__ void mma_bf16(float* d, const uint32_t* a, const uint32_t* b) {
    asm volatile(
        "mma.sync.aligned.m16n8k16.row.col.f32.bf16.bf16.f32 "
        "{%0,%1,%2,%3}, {%4,%5,%6,%7}, {%8,%9}, {%0,%1,%2,%3};"
        : "+f"(d[0]), "+f"(d[1]), "+f"(d[2]), "+f"(d[3])
        : "r"(a[0]), "r"(a[1]), "r"(a[2]), "r"(a[3]), "r"(b[0]), "r"(b[1]));
}
__device__ __forceinline__ uint32_t smem_u32(const void* p) {
    uint32_t a;
    asm("{ .reg .u64 t; cvta.to.shared.u64 t, %1; cvt.u32.u64 %0, t; }" : "=r"(a) : "l"(p));
    return a;
}
__device__ __forceinline__ void ldsm_x4(uint32_t addr, uint32_t* r) {
    asm volatile("ldmatrix.sync.aligned.m8n8.x4.shared.b16 {%0,%1,%2,%3}, [%4];"
        : "=r"(r[0]), "=r"(r[1]), "=r"(r[2]), "=r"(r[3]) : "r"(addr));
}
__device__ __forceinline__ void ldsm_x4_t(uint32_t addr, uint32_t* r) {
    asm volatile("ldmatrix.sync.aligned.m8n8.x4.trans.shared.b16 {%0,%1,%2,%3}, [%4];"
        : "=r"(r[0]), "=r"(r[1]), "=r"(r[2]), "=r"(r[3]) : "r"(addr));
}
__device__ __forceinline__ void cp16(uint32_t saddr, const void* g) {
    asm volatile("cp.async.cg.shared.global [%0], [%1], 16;" :: "r"(saddr), "l"(g));
}
__device__ __forceinline__ void cp4(uint32_t saddr, const void* g) {
    asm volatile("cp.async.ca.shared.global [%0], [%1], 4;" :: "r"(saddr), "l"(g));
}
__device__ __forceinline__ void cp_commit() {
    asm volatile("cp.async.commit_group;" ::: "memory");
}
template <int N>
__device__ __forceinline__ void cp_wait() {
    asm volatile("cp.async.wait_group %0;" :: "n"(N) : "memory");
}

// ============================================================================
// Fused QKV projection on mma.sync (split-bf16 3-term fp32 emulation).
// CTA tile 128x128, BK=32, double-buffered smem, 8 warps of 64x32.
// Epilogue writes split bf16 hi/lo directly (consumed by attention).
// ============================================================================
#define BK 32
#define NSTEP (DMODEL / BK)
#define APAD_K 40
#define TILE_HB (128 * APAD_K)
#define QKV_SMEM_BYTES (2 * 4 * TILE_HB * 2)   // 81920

__global__ __launch_bounds__(256, 1) void qkv_mma_kernel(
    const float* __restrict__ X,
    const float* __restrict__ Wq, const float* __restrict__ bq,
    const float* __restrict__ Wk, const float* __restrict__ bk,
    const float* __restrict__ Wv, const float* __restrict__ bv)
{
    extern __shared__ __nv_bfloat16 smem[];
    const int sel = blockIdx.z;
    const float* W    = (sel == 0) ? Wq : (sel == 1) ? Wk : Wv;
    const float* bias = (sel == 0) ? bq : (sel == 1) ? bk : bv;
    __nv_bfloat16* outh = (sel == 0) ? g_qh : (sel == 1) ? g_kh : g_vh;
    __nv_bfloat16* outl = (sel == 0) ? g_ql : (sel == 1) ? g_kl : g_vl;

    const int t    = threadIdx.x;
    const int lane = t & 31;
    const int w    = t >> 5;
    const int m0   = blockIdx.y * 128;
    const int n0   = blockIdx.x * 128;
    const int wm   = (w >> 2) * 64;
    const int wn   = (w & 3) * 32;

    __nv_bfloat16* Ah[2]; __nv_bfloat16* Al[2];
    __nv_bfloat16* Bh[2]; __nv_bfloat16* Bl[2];
    #pragma unroll
    for (int bf = 0; bf < 2; bf++) {
        __nv_bfloat16* base = smem + bf * 4 * TILE_HB;
        Ah[bf] = base;
        Al[bf] = base + TILE_HB;
        Bh[bf] = base + 2 * TILE_HB;
        Bl[bf] = base + 3 * TILE_HB;
    }

    const int arow = t >> 1;
    const int akc0 = (t & 1) * 16;
    const int bn   = t & 127;
    const int bkc0 = (t >> 7) * 16;

    float lda[16];
    float ldb[16];

    auto gload = [&](int ks) {
        const float* xr = X + (size_t)(m0 + arow) * DMODEL + ks * BK + akc0;
        #pragma unroll
        for (int i = 0; i < 4; i++)
            *(float4*)&lda[i * 4] = *(const float4*)(xr + i * 4);
        const float* wr = W + (size_t)(ks * BK + bkc0) * DMODEL + n0 + bn;
        #pragma unroll
        for (int i = 0; i < 16; i++)
            ldb[i] = wr[(size_t)i * DMODEL];
    };
    auto sstore = [&](int bf) {
        #pragma unroll
        for (int i = 0; i < 4; i++) {
            uint2 hp, lp;
            split2_pack(lda[i*4+0], lda[i*4+1], hp.x, lp.x);
            split2_pack(lda[i*4+2], lda[i*4+3], hp.y, lp.y);
            int off = arow * APAD_K + akc0 + i * 4;
            *(uint2*)&Ah[bf][off] = hp;
            *(uint2*)&Al[bf][off] = lp;
        }
        #pragma unroll
        for (int i = 0; i < 16; i += 2) {
            uint32_t hh, ll;
            split2_pack(ldb[i], ldb[i + 1], hh, ll);
            int off = bn * APAD_K + bkc0 + i;
            *(uint32_t*)&Bh[bf][off] = hh;
            *(uint32_t*)&Bl[bf][off] = ll;
        }
    };

    float acc[4][4][4] = {};

    gload(0);
    sstore(0);
    __syncthreads();

    for (int ks = 0; ks < NSTEP; ks++) {
        const int cur = ks & 1;
        if (ks + 1 < NSTEP) gload(ks + 1);

        #pragma unroll
        for (int kk = 0; kk < BK; kk += 16) {
            uint32_t ah[4][4], al[4][4];
            #pragma unroll
            for (int mt = 0; mt < 4; mt++) {
                int r = wm + mt * 16 + (lane >> 2);
                int k = kk + (lane & 3) * 2;
                int o0 = r * APAD_K + k;
                int o1 = (r + 8) * APAD_K + k;
                ah[mt][0] = *(uint32_t*)&Ah[cur][o0];
                ah[mt][1] = *(uint32_t*)&Ah[cur][o1];
                ah[mt][2] = *(uint32_t*)&Ah[cur][o0 + 8];
                ah[mt][3] = *(uint32_t*)&Ah[cur][o1 + 8];
                al[mt][0] = *(uint32_t*)&Al[cur][o0];
                al[mt][1] = *(uint32_t*)&Al[cur][o1];
                al[mt][2] = *(uint32_t*)&Al[cur][o0 + 8];
                al[mt][3] = *(uint32_t*)&Al[cur][o1 + 8];
            }
            #pragma unroll
            for (int nt = 0; nt < 4; nt++) {
                int n = wn + nt * 8 + (lane >> 2);
                int k = kk + (lane & 3) * 2;
                int o = n * APAD_K + k;
                uint32_t bh[2], bl[2];
                bh[0] = *(uint32_t*)&Bh[cur][o];
                bh[1] = *(uint32_t*)&Bh[cur][o + 8];
                bl[0] = *(uint32_t*)&Bl[cur][o];
                bl[1] = *(uint32_t*)&Bl[cur][o + 8];
                #pragma unroll
                for (int mt = 0; mt < 4; mt++) {
                    mma_bf16(acc[mt][nt], ah[mt], bh);
                    mma_bf16(acc[mt][nt], ah[mt], bl);
                    mma_bf16(acc[mt][nt], al[mt], bh);
                }
            }
        }

        if (ks + 1 < NSTEP) {
            sstore((ks + 1) & 1);
            __syncthreads();
        }
    }

    // Epilogue: add bias, split into bf16 hi/lo, scatter to [B,H,S,HD]
    #pragma unroll
    for (int mt = 0; mt < 4; mt++) {
        #pragma unroll
        for (int half = 0; half < 2; half++) {
            int m = m0 + wm + mt * 16 + (lane >> 2) + half * 8;
            int b = m >> 11;
            int s = m & 2047;
            size_t rowbase = (((size_t)(b * NH)) * SEQ + s) * HD;
            #pragma unroll
            for (int nt = 0; nt < 4; nt++) {
                int ncol = n0 + wn + nt * 8 + ((lane & 3) << 1);
                int h  = ncol >> 6;
                int hd = ncol & 63;
                float va = acc[mt][nt][half * 2 + 0] + bias[ncol];
                float vb = acc[mt][nt][half * 2 + 1] + bias[ncol + 1];
                uint32_t hi, lo;
                split2_pack(va, vb, hi, lo);
                size_t idx = rowbase + (size_t)h * SEQ * HD + hd;
                *(uint32_t*)&outh[idx] = hi;
                *(uint32_t*)&outl[idx] = lo;
            }
        }
    }
}

// ============================================================================
// Flash attention on mma.sync: cp.async double-buffered staging + ldmatrix
// fragment loads. CTA = 64 q-rows x (b,h); 4 warps x 16 rows; KV tile 64.
// Q/K 3-term split; P 3-term split; V 2-term split (all bf16 hi/lo).
// ============================================================================
#define KSTR 72                          // bf16 row stride (conflict-free LDSM)
#define TILEB_BYTES (64 * KSTR * 2)      // 9216
#define BUFB (4 * TILEB_BYTES)           // Kh, Kl, Vh, Vl = 36864
#define ATTN_SMEM (2 * BUFB + 2 * 256)   // + 2 mask buffers = 74240

__global__ __launch_bounds__(128, 3) void attn_mma_kernel(
    const float* __restrict__ mask,
    float* __restrict__ out)
{
    extern __shared__ char asmem[];
    const uint32_t sbase = smem_u32(asmem);

    const int t    = threadIdx.x;
    const int lane = t & 31;
    const int w    = t >> 5;
    const int lq   = lane >> 2;
    const int lr   = lane & 3;
    const int bh   = blockIdx.y;
    const int b    = bh >> 4;
    const int h    = bh & 15;
    const int q0   = blockIdx.x << 6;

    const __nv_bfloat16* Qh_g = g_qh + ((size_t)bh * SEQ + q0) * HD;
    const __nv_bfloat16* Ql_g = g_ql + ((size_t)bh * SEQ + q0) * HD;
    const __nv_bfloat16* Kh_g = g_kh + (size_t)bh * SEQ * HD;
    const __nv_bfloat16* Kl_g = g_kl + (size_t)bh * SEQ * HD;
    const __nv_bfloat16* Vh_g = g_vh + (size_t)bh * SEQ * HD;
    const __nv_bfloat16* Vl_g = g_vl + (size_t)bh * SEQ * HD;
    const float* mb = mask + (size_t)b * SEQ;

    // ldmatrix lane offsets (bytes)
    const int row_in = lane & 7;
    const int b3 = (lane >> 3) & 1;
    const int b4 = (lane >> 4) & 1;
    const uint32_t lane_k_off = ((8 * b4 + row_in) * KSTR + 8 * b3) * 2;          // K: non-trans
    const uint32_t lane_v_off = ((8 * b3 + row_in) * KSTR + 8 * b4) * 2;          // V: trans
    const uint32_t lane_q_off = ((16 * w + 8 * b3 + row_in) * KSTR + 8 * b4) * 2; // Q: A-frag

    // staging indices: thread covers 16B chunk (t&7) of row (t>>3), 4 row-passes
    const int srow = t >> 3;
    const int scol = (t & 7) * 8;   // bf16 col

    // ---- Q fragments: copy Q tile into buf0 K area, then ldmatrix ----
    #pragma unroll
    for (int p = 0; p < 4; p++) {
        int row = srow + p * 16;
        int go  = row * HD + scol;
        int so  = (row * KSTR + scol) * 2;
        *(uint4*)(asmem + so)               = *(const uint4*)(Qh_g + go);
        *(uint4*)(asmem + TILEB_BYTES + so) = *(const uint4*)(Ql_g + go);
    }
    __syncthreads();
    uint32_t qh[4][4], ql[4][4];
    #pragma unroll
    for (int t4 = 0; t4 < 4; t4++) {
        ldsm_x4(sbase + lane_q_off + 32 * t4, qh[t4]);
        ldsm_x4(sbase + TILEB_BYTES + lane_q_off + 32 * t4, ql[t4]);
    }
    __syncthreads();

    float o[8][4] = {};
    float mA = -1.0e30f, mB = -1.0e30f, lA = 0.0f, lB = 0.0f;

    auto stage = [&](int buf, int kt) {
        uint32_t sb = sbase + buf * BUFB;
        const __nv_bfloat16* kh = Kh_g + kt * HD;
        const __nv_bfloat16* kl = Kl_g + kt * HD;
        const __nv_bfloat16* vh = Vh_g + kt * HD;
        const __nv_bfloat16* vl = Vl_g + kt * HD;
        #pragma unroll
        for (int p = 0; p < 4; p++) {
            int row = srow + p * 16;
            uint32_t go = row * HD + scol;
            uint32_t so = (row * KSTR + scol) * 2;
            cp16(sb + so,                   kh + go);
            cp16(sb + TILEB_BYTES + so,     kl + go);
            cp16(sb + 2 * TILEB_BYTES + so, vh + go);
            cp16(sb + 3 * TILEB_BYTES + so, vl + go);
        }
        if (t < 64) cp4(sbase + 2 * BUFB + buf * 256 + t * 4, mb + kt + t);
        cp_commit();
    };

    stage(0, 0);

    for (int it = 0; it < SEQ / 64; it++) {
        const int cur = it & 1;
        if (it + 1 < SEQ / 64) {
            stage(cur ^ 1, (it + 1) * 64);
            cp_wait<1>();
        } else {
            cp_wait<0>();
        }
        __syncthreads();

        const float* msk = (const float*)(asmem + 2 * BUFB + cur * 256);
        const uint32_t khb = sbase + cur * BUFB + lane_k_off;
        const uint32_t klb = khb + TILEB_BYTES;

        // ---- scores (3-term split) via ldmatrix x4 ----
        float s[8][4] = {};
        #pragma unroll
        for (int t4 = 0; t4 < 4; t4++) {
            #pragma unroll
            for (int jp = 0; jp < 4; jp++) {
                uint32_t off = (16 * jp * KSTR + 16 * t4) * 2;
                uint32_t kh4[4], kl4[4];
                ldsm_x4(khb + off, kh4);
                ldsm_x4(klb + off, kl4);
                mma_bf16(s[2*jp],     qh[t4], kh4);
                mma_bf16(s[2*jp],     qh[t4], kl4);
                mma_bf16(s[2*jp],     ql[t4], kh4);
                mma_bf16(s[2*jp+1],   qh[t4], kh4 + 2);
                mma_bf16(s[2*jp+1],   qh[t4], kl4 + 2);
                mma_bf16(s[2*jp+1],   ql[t4], kh4 + 2);
            }
        }

        // ---- scale + mask ----
        #pragma unroll
        for (int j = 0; j < 8; j++) {
            float m0v = msk[8 * j + 2 * lr];
            float m1v = msk[8 * j + 2 * lr + 1];
            s[j][0] = s[j][0] * 0.125f + m0v;
            s[j][1] = s[j][1] * 0.125f + m1v;
            s[j][2] = s[j][2] * 0.125f + m0v;
            s[j][3] = s[j][3] * 0.125f + m1v;
        }

        // ---- online softmax ----
        float tmA = -1.0e30f, tmB = -1.0e30f;
        #pragma unroll
        for (int j = 0; j < 8; j++) {
            tmA = fmaxf(tmA, fmaxf(s[j][0], s[j][1]));
            tmB = fmaxf(tmB, fmaxf(s[j][2], s[j][3]));
        }
        tmA = fmaxf(tmA, __shfl_xor_sync(0xffffffffu, tmA, 1));
        tmA = fmaxf(tmA, __shfl_xor_sync(0xffffffffu, tmA, 2));
        tmB = fmaxf(tmB, __shfl_xor_sync(0xffffffffu, tmB, 1));
        tmB = fmaxf(tmB, __shfl_xor_sync(0xffffffffu, tmB, 2));
        float mAn = fmaxf(mA, tmA);
        float mBn = fmaxf(mB, tmB);
        float corrA = __expf(mA - mAn);
        float corrB = __expf(mB - mBn);
        float sumA = 0.0f, sumB = 0.0f;
        #pragma unroll
        for (int j = 0; j < 8; j++) {
            s[j][0] = __expf(s[j][0] - mAn);
            s[j][1] = __expf(s[j][1] - mAn);
            s[j][2] = __expf(s[j][2] - mBn);
            s[j][3] = __expf(s[j][3] - mBn);
            sumA += s[j][0] + s[j][1];
            sumB += s[j][2] + s[j][3];
        }
        sumA += __shfl_xor_sync(0xffffffffu, sumA, 1);
        sumA += __shfl_xor_sync(0xffffffffu, sumA, 2);
        sumB += __shfl_xor_sync(0xffffffffu, sumB, 1);
        sumB += __shfl_xor_sync(0xffffffffu, sumB, 2);
        lA = lA * corrA + sumA;
        lB = lB * corrB + sumB;
        mA = mAn;
        mB = mBn;
        #pragma unroll
        for (int j = 0; j < 8; j++) {
            o[j][0] *= corrA;
            o[j][1] *= corrA;
            o[j][2] *= corrB;
            o[j][3] *= corrB;
        }

        // ---- PV (P split 3-term) via ldmatrix.trans x4 ----
        const uint32_t vhb = sbase + cur * BUFB + 2 * TILEB_BYTES + lane_v_off;
        const uint32_t vlb = vhb + TILEB_BYTES;
        #pragma unroll
        for (int t4 = 0; t4 < 4; t4++) {
            uint32_t pfh[4], pfl[4];
            split2_pack(s[2*t4][0],   s[2*t4][1],   pfh[0], pfl[0]);
            split2_pack(s[2*t4][2],   s[2*t4][3],   pfh[1], pfl[1]);
            split2_pack(s[2*t4+1][0], s[2*t4+1][1], pfh[2], pfl[2]);
            split2_pack(s[2*t4+1][2], s[2*t4+1][3], pfh[3], pfl[3]);
            #pragma unroll
            for (int jp = 0; jp < 4; jp++) {
                uint32_t off = (16 * t4 * KSTR + 16 * jp) * 2;
                uint32_t vh4[4], vl4[4];
                ldsm_x4_t(vhb + off, vh4);
                ldsm_x4_t(vlb + off, vl4);
                mma_bf16(o[2*jp],   pfh, vh4);
                mma_bf16(o[2*jp],   pfh, vl4);
                mma_bf16(o[2*jp],   pfl, vh4);
                mma_bf16(o[2*jp+1], pfh, vh4 + 2);
                mma_bf16(o[2*jp+1], pfh, vl4 + 2);
                mma_bf16(o[2*jp+1], pfl, vh4 + 2);
            }
        }
        __syncthreads();
    }

    // ---- epilogue ----
    {
        float invA = 1.0f / lA;
        float invB = 1.0f / lB;
        int rA = q0 + 16 * w + lq;
        int rB = rA + 8;
        float* baseA = out + ((size_t)b * SEQ + rA) * DMODEL + h * HD;
        float* baseB = out + ((size_t)b * SEQ + rB) * DMODEL + h * HD;
        #pragma unroll
        for (int j = 0; j < 8; j++) {
            int col = 8 * j + 2 * lr;
            float2 ra, rb;
            ra.x = o[j][0] * invA; ra.y = o[j][1] * invA;
            rb.x = o[j][2] * invB; rb.y = o[j][3] * invB;
            *(float2*)&baseA[col] = ra;
            *(float2*)&baseB[col] = rb;
        }
    }
}

// ---------------------------------------------------------------------------
extern "C" void kernel_launch(void* const* d_in, const int* in_sizes, int n_in,
                              void* d_out, int out_size)
{
    (void)in_sizes; (void)n_in; (void)out_size;
    const float* X    = (const float*)d_in[0];
    const float* mask = (const float*)d_in[1];
    const float* Wq   = (const float*)d_in[2];
    const float* bq   = (const float*)d_in[3];
    const float* Wk   = (const float*)d_in[4];
    const float* bk   = (const float*)d_in[5];
    const float* Wv   = (const float*)d_in[6];
    const float* bv   = (const float*)d_in[7];
    float* out = (float*)d_out;

    cudaFuncSetAttribute(qkv_mma_kernel, cudaFuncAttributeMaxDynamicSharedMemorySize, QKV_SMEM_BYTES);
    dim3 gq(DMODEL / 128, (BATCH * SEQ) / 128, 3);
    qkv_mma_kernel<<<gq, 256, QKV_SMEM_BYTES>>>(X, Wq, bq, Wk, bk, Wv, bv);

    cudaFuncSetAttribute(attn_mma_kernel, cudaFuncAttributeMaxDynamicSharedMemorySize, ATTN_SMEM);
    attn_mma_kernel<<<dim3(SEQ / 64, BATCH * NH), 128, ATTN_SMEM>>>(mask, out);
}

// round 15
// speedup vs baseline: 3.1033x; 1.2988x over previous
#include <cuda_runtime.h>
#include <cuda_bf16.h>
#include <cstdint>
#include <math.h>

#define BATCH  2
#define SEQ    2048
#define DMODEL 1024
#define NH     16
#define HD     64
#define NELEM  (BATCH * NH * SEQ * HD)
#define XN     (BATCH * SEQ * DMODEL)     // 4194304
#define WN     (DMODEL * DMODEL)          // 1048576

// Q, K, V in [B, H, S, HD] layout, pre-split into bf16 hi/lo pairs.
__device__ __nv_bfloat16 g_qh[NELEM], g_ql[NELEM];
__device__ __nv_bfloat16 g_kh[NELEM], g_kl[NELEM];
__device__ __nv_bfloat16 g_vh[NELEM], g_vl[NELEM];
// X and W pre-split into bf16 hi/lo (W: 3 matrices contiguous, natural [k][n]).
__device__ __nv_bfloat16 g_xh[XN], g_xl[XN];
__device__ __nv_bfloat16 g_wh[3 * WN], g_wl[3 * WN];

// ---------------------------------------------------------------------------
__device__ __forceinline__ uint32_t bf2u(__nv_bfloat16 a, __nv_bfloat16 b) {
    __nv_bfloat162 t; t.x = a; t.y = b;
    return *reinterpret_cast<uint32_t*>(&t);
}
__device__ __forceinline__ void split_bf16(float v, __nv_bfloat16& h, __nv_bfloat16& l) {
    h = __float2bfloat16(v);
    l = __float2bfloat16(v - __bfloat162float(h));
}
__device__ __forceinline__ void split2_pack(float a, float b, uint32_t& hi, uint32_t& lo) {
    __nv_bfloat16 ha, la, hb, lb;
    split_bf16(a, ha, la);
    split_bf16(b, hb, lb);
    hi = bf2u(ha, hb);
    lo = bf2u(la, lb);
}
__device__ __forceinline__ void mma_bf16(float* d, const uint32_t* a, const uint32_t* b) {
    asm volatile(
        "mma.sync.aligned.m16n8k16.row.col.f32.bf16.bf16.f32 "
        "{%0,%1,%2,%3}, {%4,%5,%6,%7}, {%8,%9}, {%0,%1,%2,%3};"
        : "+f"(d[0]), "+f"(d[1]), "+f"(d[2]), "+f"(d[3])
        : "r"(a[0]), "r"(a[1]), "r"(a[2]), "r"(a[3]), "r"(b[0]), "r"(b[1]));
}
__device__ __forceinline__ uint32_t smem_u32(const void* p) {
    uint32_t a;
    asm("{ .reg .u64 t; cvta.to.shared.u64 t, %1; cvt.u32.u64 %0, t; }" : "=r"(a) : "l"(p));
    return a;
}
__device__ __forceinline__ void ldsm_x4(uint32_t addr, uint32_t* r) {
    asm volatile("ldmatrix.sync.aligned.m8n8.x4.shared.b16 {%0,%1,%2,%3}, [%4];"
        : "=r"(r[0]), "=r"(r[1]), "=r"(r[2]), "=r"(r[3]) : "r"(addr));
}
__device__ __forceinline__ void ldsm_x4_t(uint32_t addr, uint32_t* r) {
    asm volatile("ldmatrix.sync.aligned.m8n8.x4.trans.shared.b16 {%0,%1,%2,%3}, [%4];"
        : "=r"(r[0]), "=r"(r[1]), "=r"(r[2]), "=r"(r[3]) : "r"(addr));
}
__device__ __forceinline__ void cp16(uint32_t saddr, const void* g) {
    asm volatile("cp.async.cg.shared.global [%0], [%1], 16;" :: "r"(saddr), "l"(g));
}
__device__ __forceinline__ void cp4(uint32_t saddr, const void* g) {
    asm volatile("cp.async.ca.shared.global [%0], [%1], 4;" :: "r"(saddr), "l"(g));
}
__device__ __forceinline__ void cp_commit() {
    asm volatile("cp.async.commit_group;" ::: "memory");
}
template <int N>
__device__ __forceinline__ void cp_wait() {
    asm volatile("cp.async.wait_group %0;" :: "n"(N) : "memory");
}

// ============================================================================
// Split kernel: X, Wq, Wk, Wv (fp32) -> bf16 hi/lo global arrays.
// ============================================================================
__global__ __launch_bounds__(256) void split_kernel(
    const float* __restrict__ X,
    const float* __restrict__ Wq, const float* __restrict__ Wk,
    const float* __restrict__ Wv)
{
    size_t i4 = ((size_t)blockIdx.x * 256 + threadIdx.x) * 4;
    const float* src;
    __nv_bfloat16 *dh, *dl;
    if (i4 < XN) {
        src = X + i4;
        dh = g_xh + i4;
        dl = g_xl + i4;
    } else {
        size_t j = i4 - XN;
        int sel = (int)(j / WN);
        size_t k = j - (size_t)sel * WN;
        src = ((sel == 0) ? Wq : (sel == 1) ? Wk : Wv) + k;
        dh = g_wh + j;
        dl = g_wl + j;
    }
    float4 v = *(const float4*)src;
    uint2 hp, lp;
    split2_pack(v.x, v.y, hp.x, lp.x);
    split2_pack(v.z, v.w, hp.y, lp.y);
    *(uint2*)dh = hp;
    *(uint2*)dl = lp;
}

// ============================================================================
// QKV projection GEMM: pure bf16 (pre-split), cp.async double-buffered,
// ldmatrix fragments. CTA tile 128x128, BK=32, 8 warps of 64x32.
// 3-term: Ah*Bh + Ah*Bl + Al*Bh. gridDim.z = sel.
// ============================================================================
#define ASTR 40                       // bf16 row stride, A tiles (conflict-free)
#define BSTR 136                      // bf16 row stride, B tiles (conflict-free)
#define A_BYTES (128 * ASTR * 2)      // 10240
#define B_BYTES (32 * BSTR * 2)       // 8704
#define STAGE_B (2 * A_BYTES + 2 * B_BYTES)   // 37888 (Ah, Al, Bh, Bl)
#define QKV_SMEM2 (2 * STAGE_B)               // 75776

__global__ __launch_bounds__(256) void qkv_mma_kernel(
    const float* __restrict__ bq, const float* __restrict__ bk,
    const float* __restrict__ bv)
{
    extern __shared__ char qsmem[];
    const uint32_t sbase = smem_u32(qsmem);

    const int sel  = blockIdx.z;
    const float* bias = (sel == 0) ? bq : (sel == 1) ? bk : bv;
    __nv_bfloat16* outh = (sel == 0) ? g_qh : (sel == 1) ? g_kh : g_vh;
    __nv_bfloat16* outl = (sel == 0) ? g_ql : (sel == 1) ? g_kl : g_vl;
    const __nv_bfloat16* Wh = g_wh + (size_t)sel * WN;
    const __nv_bfloat16* Wl = g_wl + (size_t)sel * WN;

    const int t    = threadIdx.x;
    const int lane = t & 31;
    const int w    = t >> 5;
    const int lq   = lane >> 2;
    const int lr   = lane & 3;
    const int m0   = blockIdx.y * 128;
    const int n0   = blockIdx.x * 128;
    const int wm   = (w >> 2) * 64;
    const int wn   = (w & 3) * 32;

    const int row_in = lane & 7;
    const int b3 = (lane >> 3) & 1;
    const int b4 = (lane >> 4) & 1;
    const uint32_t lane_a = ((8 * b3 + row_in) * ASTR + 8 * b4) * 2;  // A non-trans
    const uint32_t lane_b = ((8 * b3 + row_in) * BSTR + 8 * b4) * 2;  // B trans

    // staging chunk indices
    const int ac_row = (t * 2) >> 2;        // A: chunks t*2, t*2+1
    const int ac_c   = (t * 2) & 3;
    const int bc_row = (t * 2) >> 4;        // B: chunks t*2, t*2+1
    const int bc_c   = (t * 2) & 15;

    auto stage = [&](int buf, int ks) {
        const int k0 = ks * 32;
        uint32_t sb = sbase + buf * STAGE_B;
        #pragma unroll
        for (int i = 0; i < 2; i++) {
            int arow = ac_row;
            int ac   = ac_c + i;           // t*2 and t*2+1 share row (4 chunks/row)
            size_t go = (size_t)(m0 + arow) * DMODEL + k0 + ac * 8;
            uint32_t so = (arow * ASTR + ac * 8) * 2;
            cp16(sb + so,            g_xh + go);
            cp16(sb + A_BYTES + so,  g_xl + go);
            int brow = bc_row;
            int bc   = bc_c + i;           // 16 chunks/row
            size_t gb = (size_t)(k0 + brow) * DMODEL + n0 + bc * 8;
            uint32_t sob = (brow * BSTR + bc * 8) * 2;
            cp16(sb + 2 * A_BYTES + sob,            Wh + gb);
            cp16(sb + 2 * A_BYTES + B_BYTES + sob,  Wl + gb);
        }
        cp_commit();
    };

    float acc[4][4][4] = {};   // [mt][2*nt + n8half][4]

    stage(0, 0);

    for (int ks = 0; ks < DMODEL / 32; ks++) {
        const int cur = ks & 1;
        if (ks + 1 < DMODEL / 32) {
            stage(cur ^ 1, ks + 1);
            cp_wait<1>();
        } else {
            cp_wait<0>();
        }
        __syncthreads();

        const uint32_t Ab  = sbase + cur * STAGE_B;
        const uint32_t Alb = Ab + A_BYTES;
        const uint32_t Bb  = Ab + 2 * A_BYTES;
        const uint32_t Blb = Bb + B_BYTES;

        #pragma unroll
        for (int kk = 0; kk < 32; kk += 16) {
            uint32_t ah[4][4], al[4][4];
            #pragma unroll
            for (int mt = 0; mt < 4; mt++) {
                uint32_t off = ((wm + 16 * mt) * ASTR + kk) * 2;
                ldsm_x4(Ab  + lane_a + off, ah[mt]);
                ldsm_x4(Alb + lane_a + off, al[mt]);
            }
            #pragma unroll
            for (int nt = 0; nt < 2; nt++) {
                uint32_t off = (kk * BSTR + wn + 16 * nt) * 2;
                uint32_t bh4[4], bl4[4];
                ldsm_x4_t(Bb  + lane_b + off, bh4);
                ldsm_x4_t(Blb + lane_b + off, bl4);
                #pragma unroll
                for (int mt = 0; mt < 4; mt++) {
                    mma_bf16(acc[mt][2*nt],   ah[mt], bh4);
                    mma_bf16(acc[mt][2*nt],   ah[mt], bl4);
                    mma_bf16(acc[mt][2*nt],   al[mt], bh4);
                    mma_bf16(acc[mt][2*nt+1], ah[mt], bh4 + 2);
                    mma_bf16(acc[mt][2*nt+1], ah[mt], bl4 + 2);
                    mma_bf16(acc[mt][2*nt+1], al[mt], bh4 + 2);
                }
            }
        }
        __syncthreads();
    }

    // Epilogue: add bias, split into bf16 hi/lo, scatter to [B,H,S,HD]
    #pragma unroll
    for (int mt = 0; mt < 4; mt++) {
        #pragma unroll
        for (int half = 0; half < 2; half++) {
            int m = m0 + wm + mt * 16 + lq + half * 8;
            int b = m >> 11;
            int s = m & 2047;
            size_t rowbase = (((size_t)(b * NH)) * SEQ + s) * HD;
            #pragma unroll
            for (int j = 0; j < 4; j++) {
                int ncol = n0 + wn + (j >> 1) * 16 + (j & 1) * 8 + 2 * lr;
                int h  = ncol >> 6;
                int hd = ncol & 63;
                float va = acc[mt][j][half * 2 + 0] + bias[ncol];
                float vb = acc[mt][j][half * 2 + 1] + bias[ncol + 1];
                uint32_t hi, lo;
                split2_pack(va, vb, hi, lo);
                size_t idx = rowbase + (size_t)h * SEQ * HD + hd;
                *(uint32_t*)&outh[idx] = hi;
                *(uint32_t*)&outl[idx] = lo;
            }
        }
    }
}

// ============================================================================
// Flash attention on mma.sync (unchanged from round 11, 713us version).
// ============================================================================
#define KSTR 72
#define TILEB_BYTES (64 * KSTR * 2)
#define BUFB (4 * TILEB_BYTES)
#define ATTN_SMEM (2 * BUFB + 2 * 256)

__global__ __launch_bounds__(128, 3) void attn_mma_kernel(
    const float* __restrict__ mask,
    float* __restrict__ out)
{
    extern __shared__ char asmem[];
    const uint32_t sbase = smem_u32(asmem);

    const int t    = threadIdx.x;
    const int lane = t & 31;
    const int w    = t >> 5;
    const int lq   = lane >> 2;
    const int lr   = lane & 3;
    const int bh   = blockIdx.y;
    const int b    = bh >> 4;
    const int h    = bh & 15;
    const int q0   = blockIdx.x << 6;

    const __nv_bfloat16* Qh_g = g_qh + ((size_t)bh * SEQ + q0) * HD;
    const __nv_bfloat16* Ql_g = g_ql + ((size_t)bh * SEQ + q0) * HD;
    const __nv_bfloat16* Kh_g = g_kh + (size_t)bh * SEQ * HD;
    const __nv_bfloat16* Kl_g = g_kl + (size_t)bh * SEQ * HD;
    const __nv_bfloat16* Vh_g = g_vh + (size_t)bh * SEQ * HD;
    const __nv_bfloat16* Vl_g = g_vl + (size_t)bh * SEQ * HD;
    const float* mb = mask + (size_t)b * SEQ;

    const int row_in = lane & 7;
    const int b3 = (lane >> 3) & 1;
    const int b4 = (lane >> 4) & 1;
    const uint32_t lane_k_off = ((8 * b4 + row_in) * KSTR + 8 * b3) * 2;
    const uint32_t lane_v_off = ((8 * b3 + row_in) * KSTR + 8 * b4) * 2;
    const uint32_t lane_q_off = ((16 * w + 8 * b3 + row_in) * KSTR + 8 * b4) * 2;

    const int srow = t >> 3;
    const int scol = (t & 7) * 8;

    #pragma unroll
    for (int p = 0; p < 4; p++) {
        int row = srow + p * 16;
        int go  = row * HD + scol;
        int so  = (row * KSTR + scol) * 2;
        *(uint4*)(asmem + so)               = *(const uint4*)(Qh_g + go);
        *(uint4*)(asmem + TILEB_BYTES + so) = *(const uint4*)(Ql_g + go);
    }
    __syncthreads();
    uint32_t qh[4][4], ql[4][4];
    #pragma unroll
    for (int t4 = 0; t4 < 4; t4++) {
        ldsm_x4(sbase + lane_q_off + 32 * t4, qh[t4]);
        ldsm_x4(sbase + TILEB_BYTES + lane_q_off + 32 * t4, ql[t4]);
    }
    __syncthreads();

    float o[8][4] = {};
    float mA = -1.0e30f, mB = -1.0e30f, lA = 0.0f, lB = 0.0f;

    auto stage = [&](int buf, int kt) {
        uint32_t sb = sbase + buf * BUFB;
        const __nv_bfloat16* kh = Kh_g + kt * HD;
        const __nv_bfloat16* kl = Kl_g + kt * HD;
        const __nv_bfloat16* vh = Vh_g + kt * HD;
        const __nv_bfloat16* vl = Vl_g + kt * HD;
        #pragma unroll
        for (int p = 0; p < 4; p++) {
            int row = srow + p * 16;
            uint32_t go = row * HD + scol;
            uint32_t so = (row * KSTR + scol) * 2;
            cp16(sb + so,                   kh + go);
            cp16(sb + TILEB_BYTES + so,     kl + go);
            cp16(sb + 2 * TILEB_BYTES + so, vh + go);
            cp16(sb + 3 * TILEB_BYTES + so, vl + go);
        }
        if (t < 64) cp4(sbase + 2 * BUFB + buf * 256 + t * 4, mb + kt + t);
        cp_commit();
    };

    stage(0, 0);

    for (int it = 0; it < SEQ / 64; it++) {
        const int cur = it & 1;
        if (it + 1 < SEQ / 64) {
            stage(cur ^ 1, (it + 1) * 64);
            cp_wait<1>();
        } else {
            cp_wait<0>();
        }
        __syncthreads();

        const float* msk = (const float*)(asmem + 2 * BUFB + cur * 256);
        const uint32_t khb = sbase + cur * BUFB + lane_k_off;
        const uint32_t klb = khb + TILEB_BYTES;

        float s[8][4] = {};
        #pragma unroll
        for (int t4 = 0; t4 < 4; t4++) {
            #pragma unroll
            for (int jp = 0; jp < 4; jp++) {
                uint32_t off = (16 * jp * KSTR + 16 * t4) * 2;
                uint32_t kh4[4], kl4[4];
                ldsm_x4(khb + off, kh4);
                ldsm_x4(klb + off, kl4);
                mma_bf16(s[2*jp],     qh[t4], kh4);
                mma_bf16(s[2*jp],     qh[t4], kl4);
                mma_bf16(s[2*jp],     ql[t4], kh4);
                mma_bf16(s[2*jp+1],   qh[t4], kh4 + 2);
                mma_bf16(s[2*jp+1],   qh[t4], kl4 + 2);
                mma_bf16(s[2*jp+1],   ql[t4], kh4 + 2);
            }
        }

        #pragma unroll
        for (int j = 0; j < 8; j++) {
            float m0v = msk[8 * j + 2 * lr];
            float m1v = msk[8 * j + 2 * lr + 1];
            s[j][0] = s[j][0] * 0.125f + m0v;
            s[j][1] = s[j][1] * 0.125f + m1v;
            s[j][2] = s[j][2] * 0.125f + m0v;
            s[j][3] = s[j][3] * 0.125f + m1v;
        }

        float tmA = -1.0e30f, tmB = -1.0e30f;
        #pragma unroll
        for (int j = 0; j < 8; j++) {
            tmA = fmaxf(tmA, fmaxf(s[j][0], s[j][1]));
            tmB = fmaxf(tmB, fmaxf(s[j][2], s[j][3]));
        }
        tmA = fmaxf(tmA, __shfl_xor_sync(0xffffffffu, tmA, 1));
        tmA = fmaxf(tmA, __shfl_xor_sync(0xffffffffu, tmA, 2));
        tmB = fmaxf(tmB, __shfl_xor_sync(0xffffffffu, tmB, 1));
        tmB = fmaxf(tmB, __shfl_xor_sync(0xffffffffu, tmB, 2));
        float mAn = fmaxf(mA, tmA);
        float mBn = fmaxf(mB, tmB);
        float corrA = __expf(mA - mAn);
        float corrB = __expf(mB - mBn);
        float sumA = 0.0f, sumB = 0.0f;
        #pragma unroll
        for (int j = 0; j < 8; j++) {
            s[j][0] = __expf(s[j][0] - mAn);
            s[j][1] = __expf(s[j][1] - mAn);
            s[j][2] = __expf(s[j][2] - mBn);
            s[j][3] = __expf(s[j][3] - mBn);
            sumA += s[j][0] + s[j][1];
            sumB += s[j][2] + s[j][3];
        }
        sumA += __shfl_xor_sync(0xffffffffu, sumA, 1);
        sumA += __shfl_xor_sync(0xffffffffu, sumA, 2);
        sumB += __shfl_xor_sync(0xffffffffu, sumB, 1);
        sumB += __shfl_xor_sync(0xffffffffu, sumB, 2);
        lA = lA * corrA + sumA;
        lB = lB * corrB + sumB;
        mA = mAn;
        mB = mBn;
        #pragma unroll
        for (int j = 0; j < 8; j++) {
            o[j][0] *= corrA;
            o[j][1] *= corrA;
            o[j][2] *= corrB;
            o[j][3] *= corrB;
        }

        const uint32_t vhb = sbase + cur * BUFB + 2 * TILEB_BYTES + lane_v_off;
        const uint32_t vlb = vhb + TILEB_BYTES;
        #pragma unroll
        for (int t4 = 0; t4 < 4; t4++) {
            uint32_t pfh[4], pfl[4];
            split2_pack(s[2*t4][0],   s[2*t4][1],   pfh[0], pfl[0]);
            split2_pack(s[2*t4][2],   s[2*t4][3],   pfh[1], pfl[1]);
            split2_pack(s[2*t4+1][0], s[2*t4+1][1], pfh[2], pfl[2]);
            split2_pack(s[2*t4+1][2], s[2*t4+1][3], pfh[3], pfl[3]);
            #pragma unroll
            for (int jp = 0; jp < 4; jp++) {
                uint32_t off = (16 * t4 * KSTR + 16 * jp) * 2;
                uint32_t vh4[4], vl4[4];
                ldsm_x4_t(vhb + off, vh4);
                ldsm_x4_t(vlb + off, vl4);
                mma_bf16(o[2*jp],   pfh, vh4);
                mma_bf16(o[2*jp],   pfh, vl4);
                mma_bf16(o[2*jp],   pfl, vh4);
                mma_bf16(o[2*jp+1], pfh, vh4 + 2);
                mma_bf16(o[2*jp+1], pfh, vl4 + 2);
                mma_bf16(o[2*jp+1], pfl, vh4 + 2);
            }
        }
        __syncthreads();
    }

    {
        float invA = 1.0f / lA;
        float invB = 1.0f / lB;
        int rA = q0 + 16 * w + lq;
        int rB = rA + 8;
        float* baseA = out + ((size_t)b * SEQ + rA) * DMODEL + h * HD;
        float* baseB = out + ((size_t)b * SEQ + rB) * DMODEL + h * HD;
        #pragma unroll
        for (int j = 0; j < 8; j++) {
            int col = 8 * j + 2 * lr;
            float2 ra, rb;
            ra.x = o[j][0] * invA; ra.y = o[j][1] * invA;
            rb.x = o[j][2] * invB; rb.y = o[j][3] * invB;
            *(float2*)&baseA[col] = ra;
            *(float2*)&baseB[col] = rb;
        }
    }
}

// ---------------------------------------------------------------------------
extern "C" void kernel_launch(void* const* d_in, const int* in_sizes, int n_in,
                              void* d_out, int out_size)
{
    (void)in_sizes; (void)n_in; (void)out_size;
    const float* X    = (const float*)d_in[0];
    const float* mask = (const float*)d_in[1];
    const float* Wq   = (const float*)d_in[2];
    const float* bq   = (const float*)d_in[3];
    const float* Wk   = (const float*)d_in[4];
    const float* bk   = (const float*)d_in[5];
    const float* Wv   = (const float*)d_in[6];
    const float* bv   = (const float*)d_in[7];
    float* out = (float*)d_out;

    split_kernel<<<(XN + 3 * WN) / (4 * 256), 256>>>(X, Wq, Wk, Wv);

    cudaFuncSetAttribute(qkv_mma_kernel, cudaFuncAttributeMaxDynamicSharedMemorySize, QKV_SMEM2);
    dim3 gq(DMODEL / 128, (BATCH * SEQ) / 128, 3);
    qkv_mma_kernel<<<gq, 256, QKV_SMEM2>>>(bq, bk, bv);

    cudaFuncSetAttribute(attn_mma_kernel, cudaFuncAttributeMaxDynamicSharedMemorySize, ATTN_SMEM);
    attn_mma_kernel<<<dim3(SEQ / 64, BATCH * NH), 128, ATTN_SMEM>>>(mask, out);
}